// round 16
// baseline (speedup 1.0000x reference)
#include <cuda_runtime.h>

#define BB 64
#define FF 128
#define LL 8192
#define KK 16
#define TILE 128
#define NTILES (LL / TILE)      // 64
#define RS 132                  // padded SMEM row stride (floats)
#define TSZ (64 * RS)           // 8448 floats per tile buffer

typedef unsigned long long u64;

__device__ float g_partial[128 * LL];   // per-(batch,half) partial logits max

__device__ __forceinline__ u64 fma2(u64 a, u64 b, u64 c) {
    u64 d;
    asm("fma.rn.f32x2 %0, %1, %2, %3;" : "=l"(d) : "l"(a), "l"(b), "l"(c));
    return d;
}
__device__ __forceinline__ u64 pack2(float lo, float hi) {
    u64 d; asm("mov.b64 %0, {%1, %2};" : "=l"(d) : "f"(lo), "f"(hi)); return d;
}
__device__ __forceinline__ void unpack2(u64 v, float& lo, float& hi) {
    asm("mov.b64 {%0, %1}, %2;" : "=f"(lo), "=f"(hi) : "l"(v));
}
__device__ __forceinline__ void stcs4(float* p, float4 v) {
    asm volatile("st.global.cs.v4.f32 [%0], {%1,%2,%3,%4};"
                 :: "l"(p), "f"(v.x), "f"(v.y), "f"(v.z), "f"(v.w) : "memory");
}
__device__ __forceinline__ float4 max4(float4 a, float4 b) {
    return make_float4(fmaxf(a.x, b.x), fmaxf(a.y, b.y),
                       fmaxf(a.z, b.z), fmaxf(a.w, b.w));
}

// ---------------------------------------------------------------------------
// conv: one column half (16 quads, 64 cols) for fixed filter f. f32x2 FMAs.
// xs[p] = x[tile*128 - 15 + p]; xsh[q] = xs[q+1] (odd-parity pairs).
// ---------------------------------------------------------------------------
__device__ __forceinline__ void conv_do(
    int qh, const float* __restrict__ xs, const float* __restrict__ xsh,
    const u64* __restrict__ w2, u64 bias2, float* __restrict__ irow)
{
#pragma unroll
    for (int j = 0; j < 16; ++j) {
        const int lt4 = qh * 64 + 4 * j;     // even
        u64 P[18];
#pragma unroll
        for (int m = 0; m < 18; ++m) {
            int base = lt4 + m;              // parity == m parity
            P[m] = (m & 1) ? *(const u64*)(xsh + (base - 1))
                           : *(const u64*)(xs + base);
        }
        u64 a01 = bias2, a23 = bias2;
#pragma unroll
        for (int k = 0; k < KK; ++k) {
            a01 = fma2(w2[k], P[k],     a01);
            a23 = fma2(w2[k], P[k + 2], a23);
        }
        float o0, o1, o2, o3;
        unpack2(a01, o0, o1);
        unpack2(a23, o2, o3);
        *(float4*)(irow + lt4) = make_float4(o0, o1, o2, o3);
    }
}

// ---------------------------------------------------------------------------
// Fused conv + LIF + coalesced streaming stores + fused logits partial max.
// LSU-issue rebalanced: conv warps also store I(T) (data is read-only in
// Ibuf[buf] for the whole iteration), freeing flush-warp issue slack.
// Grid 128 = (batch, filter-half), 256 threads:
//   tid   0- 63 : chain warps — LIF recurrence -> v_pre tiles in SMEM
//   tid  64-191 : conv warps  — STG I(T) from Ibuf[buf]; f32x2 conv of
//                               tile T+1 into Ibuf[buf^1] (double-buffered)
//   tid 192-255 : flush warps — STG v_pre/v/s(T-1) with derive;
//                               column-max -> g_partial
// ---------------------------------------------------------------------------
__global__ __launch_bounds__(256, 1) void snn_fused(
    const float* __restrict__ x, const float* __restrict__ W,
    const float* __restrict__ bias,
    float* __restrict__ I_out, float* __restrict__ vpre_out,
    float* __restrict__ v_out, float* __restrict__ s_out)
{
    extern __shared__ float sm[];
    float* Ibuf = sm;                 // 2*TSZ
    float* tvp  = sm + 2 * TSZ;       // 2*TSZ
    float* xs   = sm + 4 * TSZ;       // 144 (143 used)
    float* xsh  = xs + 144;           // 144
    float* red  = xsh + 144;          // 256

    const int tid   = threadIdx.x;
    const int b     = blockIdx.x >> 1;
    const int h     = blockIdx.x & 1;
    const int frow0 = b * FF + h * 64;          // OUTPUT row base
    const float* __restrict__ xb = x + (size_t)b * LL;
    float* __restrict__ prow = g_partial + (size_t)blockIdx.x * LL;

    // conv-thread persistent state (filter index is batch-INDEPENDENT)
    u64 w2[KK];
    u64 bias2 = 0;
    int f_loc = 0, qh = 0;
    if (tid >= 64 && tid < 192) {
        const int p = tid - 64;
        f_loc = p >> 1; qh = p & 1;
        const int fflt = h * 64 + f_loc;        // filter index 0..127
#pragma unroll
        for (int k = 0; k < KK; ++k) {
            const float w = W[fflt * KK + k];
            w2[k] = pack2(w, w);
        }
        const float bv = bias[fflt];
        bias2 = pack2(bv, bv);
    }

    // ---- prologue: stage xs(tile0), conv tile0 -> Ibuf[0] ----
    if (tid >= 64 && tid < 192) {
        const int p = tid - 64;
        {
            int g = p - 15;
            float val = (g >= 0) ? xb[g] : 0.0f;
            xs[p] = val;
            if (p >= 1) xsh[p - 1] = val;
        }
        if (p < 15) {
            int idx = 128 + p;
            float val = xb[idx - 15];
            xs[idx] = val;
            xsh[idx - 1] = val;
        }
        asm volatile("bar.sync 1, 128;" ::: "memory");
        conv_do(qh, xs, xsh, w2, bias2, Ibuf + f_loc * RS);
    }
    __syncthreads();

    float vchain = 0.0f;

    for (int T = 0; T < NTILES; ++T) {
        const int buf = T & 1;
        if (tid < 64) {
            // ---------------- chain ----------------
            const float* ir = Ibuf + buf * TSZ + tid * RS;
            float* vr = tvp + buf * TSZ + tid * RS;
            float4 cur = *(const float4*)ir;
#pragma unroll
            for (int q = 0; q < 32; ++q) {
                float4 nxt = (q < 31) ? *(const float4*)(ir + 4 * (q + 1)) : cur;
                const float c0 = 0.2f * cur.x, c1 = 0.2f * cur.y;
                const float c2 = 0.2f * cur.z, c3 = 0.2f * cur.w;
                float vp0 = fmaf(vchain, 0.8f, c0);
                vchain = (vp0 >= 1.0f) ? 0.0f : vp0;
                float vp1 = fmaf(vchain, 0.8f, c1);
                vchain = (vp1 >= 1.0f) ? 0.0f : vp1;
                float vp2 = fmaf(vchain, 0.8f, c2);
                vchain = (vp2 >= 1.0f) ? 0.0f : vp2;
                float vp3 = fmaf(vchain, 0.8f, c3);
                vchain = (vp3 >= 1.0f) ? 0.0f : vp3;
                *(float4*)(vr + 4 * q) = make_float4(vp0, vp1, vp2, vp3);
                cur = nxt;
            }
        } else if (tid < 192) {
            // ---------------- conv (+ I(T) store) ----------------
            const int p = tid - 64;
            // store I(T) coalesced from Ibuf[buf] — read-only this iteration;
            // issued first so the STGs drain under the conv FMAs below.
            {
                const int tq = p & 31, r0c = p >> 5;   // 4 rows per thread grp
                const float* ib = Ibuf + buf * TSZ;
                const size_t tcol = (size_t)T * TILE + tq * 4;
#pragma unroll
                for (int i = 0; i < 16; ++i) {
                    const int r = r0c + 4 * i;
                    stcs4(I_out + (size_t)(frow0 + r) * LL + tcol,
                          *(const float4*)(ib + r * RS + tq * 4));
                }
            }
            if (T + 1 < NTILES) {
                {
                    int g = (T + 1) * TILE - 15 + p;   // >= 113, valid
                    float val = xb[g];
                    xs[p] = val;
                    if (p >= 1) xsh[p - 1] = val;
                }
                if (p < 15) {
                    int idx = 128 + p;
                    float val = xb[(T + 1) * TILE - 15 + idx];
                    xs[idx] = val;
                    xsh[idx - 1] = val;
                }
                asm volatile("bar.sync 1, 128;" ::: "memory");
                conv_do(qh, xs, xsh, w2, bias2,
                        Ibuf + ((T + 1) & 1) * TSZ + f_loc * RS);
            }
        } else {
            // ---------------- flush (v_pre/v/s only) ----------------
            const int ft = tid - 192;
            const int r0 = ft >> 5, tq = ft & 31;    // warp covers full rows
            const float* vpb = tvp + (buf ^ 1) * TSZ;
            const size_t pcol = (size_t)(T - 1) * TILE + tq * 4;
            float4 mx = make_float4(-1e30f, -1e30f, -1e30f, -1e30f);
            if (T >= 1) {
#pragma unroll
                for (int i = 0; i < 32; ++i) {
                    const int r = r0 + 2 * i;
                    const size_t grow = (size_t)(frow0 + r) * LL;
                    float4 vq = *(const float4*)(vpb + r * RS + tq * 4);
                    float4 sq, vn;
                    sq.x = (vq.x >= 1.0f) ? 1.0f : 0.0f;
                    sq.y = (vq.y >= 1.0f) ? 1.0f : 0.0f;
                    sq.z = (vq.z >= 1.0f) ? 1.0f : 0.0f;
                    sq.w = (vq.w >= 1.0f) ? 1.0f : 0.0f;
                    vn.x = (vq.x >= 1.0f) ? 0.0f : vq.x;
                    vn.y = (vq.y >= 1.0f) ? 0.0f : vq.y;
                    vn.z = (vq.z >= 1.0f) ? 0.0f : vq.z;
                    vn.w = (vq.w >= 1.0f) ? 0.0f : vq.w;
                    stcs4(vpre_out + grow + pcol, vq);
                    stcs4(v_out    + grow + pcol, vn);
                    stcs4(s_out    + grow + pcol, sq);
                    mx = max4(mx, vq);
                }
                *(float4*)(red + ft * 4) = mx;
                asm volatile("bar.sync 3, 64;" ::: "memory");
                if (ft < 32) {
                    float4 a  = *(float4*)(red + ft * 4);
                    float4 b4 = *(float4*)(red + (32 + ft) * 4);
                    a = max4(a, b4);
                    *(float4*)(prow + (size_t)(T - 1) * TILE + ft * 4) = a;
                }
            }
        }
        __syncthreads();
    }

    // ---- epilogue: flush v_pre/v/s + partial max of tile 63 (buffer 1) ----
    if (tid >= 192) {
        const int ft = tid - 192;
        const int r0 = ft >> 5, tq = ft & 31;
        const float* vpb = tvp + ((NTILES - 1) & 1) * TSZ;
        const size_t pcol = (size_t)(NTILES - 1) * TILE + tq * 4;
        float4 mx = make_float4(-1e30f, -1e30f, -1e30f, -1e30f);
#pragma unroll
        for (int i = 0; i < 32; ++i) {
            const int r = r0 + 2 * i;
            const size_t grow = (size_t)(frow0 + r) * LL;
            float4 vq = *(const float4*)(vpb + r * RS + tq * 4);
            float4 sq, vn;
            sq.x = (vq.x >= 1.0f) ? 1.0f : 0.0f;
            sq.y = (vq.y >= 1.0f) ? 1.0f : 0.0f;
            sq.z = (vq.z >= 1.0f) ? 1.0f : 0.0f;
            sq.w = (vq.w >= 1.0f) ? 1.0f : 0.0f;
            vn.x = (vq.x >= 1.0f) ? 0.0f : vq.x;
            vn.y = (vq.y >= 1.0f) ? 0.0f : vq.y;
            vn.z = (vq.z >= 1.0f) ? 0.0f : vq.z;
            vn.w = (vq.w >= 1.0f) ? 0.0f : vq.w;
            stcs4(vpre_out + grow + pcol, vq);
            stcs4(v_out    + grow + pcol, vn);
            stcs4(s_out    + grow + pcol, sq);
            mx = max4(mx, vq);
        }
        *(float4*)(red + ft * 4) = mx;
        asm volatile("bar.sync 3, 64;" ::: "memory");
        if (ft < 32) {
            float4 a  = *(float4*)(red + ft * 4);
            float4 b4 = *(float4*)(red + (32 + ft) * 4);
            a = max4(a, b4);
            *(float4*)(prow + (size_t)(NTILES - 1) * TILE + ft * 4) = a;
        }
    }
}

// ---------------------------------------------------------------------------
// Combine the two filter-half partial maxes into logits.
// MLP=4: each thread owns two float4 column-pairs (4 independent loads).
// ---------------------------------------------------------------------------
__global__ __launch_bounds__(256) void logits_kernel(float* __restrict__ logits)
{
    int i = blockIdx.x * blockDim.x + threadIdx.x;   // 0 .. BB*LL/8-1
    int b  = i >> 10;                                // 1024 pair-groups/batch
    int l4 = (i & 1023) * 2;                         // float4 index (even)
    const float4* p0 = (const float4*)(g_partial + (size_t)(2 * b) * LL) + l4;
    const float4* p1 = (const float4*)(g_partial + (size_t)(2 * b + 1) * LL) + l4;
    float4 a0 = p0[0], c0 = p1[0];
    float4 a1 = p0[1], c1 = p1[1];
    float4 m0 = max4(a0, c0);
    float4 m1 = max4(a1, c1);
    m0.x -= 1.0f; m0.y -= 1.0f; m0.z -= 1.0f; m0.w -= 1.0f;
    m1.x -= 1.0f; m1.y -= 1.0f; m1.z -= 1.0f; m1.w -= 1.0f;
    float* dst = logits + (size_t)b * LL + l4 * 4;
    stcs4(dst,     m0);
    stcs4(dst + 4, m1);
}

extern "C" void kernel_launch(void* const* d_in, const int* in_sizes, int n_in,
                              void* d_out, int out_size)
{
    const float* x    = (const float*)d_in[0];
    const float* W    = (const float*)d_in[1];
    const float* bias = (const float*)d_in[2];
    float* out = (float*)d_out;

    const size_t N = (size_t)BB * FF * LL;   // 67,108,864
    float* I    = out;
    float* vpre = out + N;
    float* vv   = out + 2 * N;
    float* ss   = out + 3 * N;
    float* lg   = out + 4 * N;

    const int smem_bytes = (4 * TSZ + 144 + 144 + 256) * sizeof(float); // ~137.4KB
    cudaFuncSetAttribute(snn_fused,
                         cudaFuncAttributeMaxDynamicSharedMemorySize, smem_bytes);

    snn_fused<<<128, 256, smem_bytes>>>(x, W, bias, I, vpre, vv, ss);
    logits_kernel<<<(BB * LL / 8) / 256, 256>>>(lg);
}

// round 17
// speedup vs baseline: 1.0440x; 1.0440x over previous
#include <cuda_runtime.h>

#define BB 64
#define FF 128
#define LL 8192
#define KK 16
#define TILE 128
#define NTILES (LL / TILE)      // 64
#define RS 132                  // padded SMEM row stride (floats)
#define TSZ (64 * RS)           // 8448 floats per tile buffer

typedef unsigned long long u64;

__device__ float g_partial[128 * LL];   // per-(batch,half) partial logits max

__device__ __forceinline__ u64 fma2(u64 a, u64 b, u64 c) {
    u64 d;
    asm("fma.rn.f32x2 %0, %1, %2, %3;" : "=l"(d) : "l"(a), "l"(b), "l"(c));
    return d;
}
__device__ __forceinline__ u64 pack2(float lo, float hi) {
    u64 d; asm("mov.b64 %0, {%1, %2};" : "=l"(d) : "f"(lo), "f"(hi)); return d;
}
__device__ __forceinline__ void unpack2(u64 v, float& lo, float& hi) {
    asm("mov.b64 {%0, %1}, %2;" : "=f"(lo), "=f"(hi) : "l"(v));
}
__device__ __forceinline__ void stcs4(float* p, float4 v) {
    asm volatile("st.global.cs.v4.f32 [%0], {%1,%2,%3,%4};"
                 :: "l"(p), "f"(v.x), "f"(v.y), "f"(v.z), "f"(v.w) : "memory");
}
__device__ __forceinline__ float4 max4(float4 a, float4 b) {
    return make_float4(fmaxf(a.x, b.x), fmaxf(a.y, b.y),
                       fmaxf(a.z, b.z), fmaxf(a.w, b.w));
}

// ---------------------------------------------------------------------------
// conv: one column half (16 quads, 64 cols) for fixed filter f. f32x2 FMAs.
// xs[p] = x[tile*128 - 15 + p]; xsh[q] = xs[q+1] (odd-parity pairs).
// ---------------------------------------------------------------------------
__device__ __forceinline__ void conv_do(
    int qh, const float* __restrict__ xs, const float* __restrict__ xsh,
    const u64* __restrict__ w2, u64 bias2, float* __restrict__ irow)
{
#pragma unroll
    for (int j = 0; j < 16; ++j) {
        const int lt4 = qh * 64 + 4 * j;     // even
        u64 P[18];
#pragma unroll
        for (int m = 0; m < 18; ++m) {
            int base = lt4 + m;              // parity == m parity
            P[m] = (m & 1) ? *(const u64*)(xsh + (base - 1))
                           : *(const u64*)(xs + base);
        }
        u64 a01 = bias2, a23 = bias2;
#pragma unroll
        for (int k = 0; k < KK; ++k) {
            a01 = fma2(w2[k], P[k],     a01);
            a23 = fma2(w2[k], P[k + 2], a23);
        }
        float o0, o1, o2, o3;
        unpack2(a01, o0, o1);
        unpack2(a23, o2, o3);
        *(float4*)(irow + lt4) = make_float4(o0, o1, o2, o3);
    }
}

// ---------------------------------------------------------------------------
// Fused conv + LIF + coalesced streaming stores + fused logits partial max.
// Grid 128 = (batch, filter-half), 256 threads:
//   tid   0- 63 : chain warps  — LIF recurrence -> v_pre tiles in SMEM
//   tid  64-191 : conv warps   — f32x2 conv of tile T+1 (double-buffered)
//   tid 192-255 : flush warps  — STG I(T); STG v_pre/v/s(T-1) with derive;
//                                column-max -> g_partial
// ---------------------------------------------------------------------------
__global__ __launch_bounds__(256, 1) void snn_fused(
    const float* __restrict__ x, const float* __restrict__ W,
    const float* __restrict__ bias,
    float* __restrict__ I_out, float* __restrict__ vpre_out,
    float* __restrict__ v_out, float* __restrict__ s_out)
{
    extern __shared__ float sm[];
    float* Ibuf = sm;                 // 2*TSZ
    float* tvp  = sm + 2 * TSZ;       // 2*TSZ
    float* xs   = sm + 4 * TSZ;       // 144 (143 used)
    float* xsh  = xs + 144;           // 144
    float* red  = xsh + 144;          // 256

    const int tid   = threadIdx.x;
    const int b     = blockIdx.x >> 1;
    const int h     = blockIdx.x & 1;
    const int frow0 = b * FF + h * 64;          // OUTPUT row base
    const float* __restrict__ xb = x + (size_t)b * LL;
    float* __restrict__ prow = g_partial + (size_t)blockIdx.x * LL;

    // conv-thread persistent state (filter index is batch-INDEPENDENT)
    u64 w2[KK];
    u64 bias2 = 0;
    int f_loc = 0, qh = 0;
    if (tid >= 64 && tid < 192) {
        const int p = tid - 64;
        f_loc = p >> 1; qh = p & 1;
        const int fflt = h * 64 + f_loc;        // filter index 0..127
#pragma unroll
        for (int k = 0; k < KK; ++k) {
            const float w = W[fflt * KK + k];
            w2[k] = pack2(w, w);
        }
        const float bv = bias[fflt];
        bias2 = pack2(bv, bv);
    }

    // ---- prologue: stage xs(tile0), conv tile0 -> Ibuf[0] ----
    if (tid >= 64 && tid < 192) {
        const int p = tid - 64;
        {
            int g = p - 15;
            float val = (g >= 0) ? xb[g] : 0.0f;
            xs[p] = val;
            if (p >= 1) xsh[p - 1] = val;
        }
        if (p < 15) {
            int idx = 128 + p;
            float val = xb[idx - 15];
            xs[idx] = val;
            xsh[idx - 1] = val;
        }
        asm volatile("bar.sync 1, 128;" ::: "memory");
        conv_do(qh, xs, xsh, w2, bias2, Ibuf + f_loc * RS);
    }
    __syncthreads();

    float vchain = 0.0f;

    for (int T = 0; T < NTILES; ++T) {
        const int buf = T & 1;
        if (tid < 64) {
            // ---------------- chain ----------------
            const float* ir = Ibuf + buf * TSZ + tid * RS;
            float* vr = tvp + buf * TSZ + tid * RS;
            float4 cur = *(const float4*)ir;
#pragma unroll
            for (int q = 0; q < 32; ++q) {
                float4 nxt = (q < 31) ? *(const float4*)(ir + 4 * (q + 1)) : cur;
                const float c0 = 0.2f * cur.x, c1 = 0.2f * cur.y;
                const float c2 = 0.2f * cur.z, c3 = 0.2f * cur.w;
                float vp0 = fmaf(vchain, 0.8f, c0);
                vchain = (vp0 >= 1.0f) ? 0.0f : vp0;
                float vp1 = fmaf(vchain, 0.8f, c1);
                vchain = (vp1 >= 1.0f) ? 0.0f : vp1;
                float vp2 = fmaf(vchain, 0.8f, c2);
                vchain = (vp2 >= 1.0f) ? 0.0f : vp2;
                float vp3 = fmaf(vchain, 0.8f, c3);
                vchain = (vp3 >= 1.0f) ? 0.0f : vp3;
                *(float4*)(vr + 4 * q) = make_float4(vp0, vp1, vp2, vp3);
                cur = nxt;
            }
        } else if (tid < 192) {
            // ---------------- conv ----------------
            const int p = tid - 64;
            if (T + 1 < NTILES) {
                {
                    int g = (T + 1) * TILE - 15 + p;   // >= 113, valid
                    float val = xb[g];
                    xs[p] = val;
                    if (p >= 1) xsh[p - 1] = val;
                }
                if (p < 15) {
                    int idx = 128 + p;
                    float val = xb[(T + 1) * TILE - 15 + idx];
                    xs[idx] = val;
                    xsh[idx - 1] = val;
                }
                asm volatile("bar.sync 1, 128;" ::: "memory");
                conv_do(qh, xs, xsh, w2, bias2,
                        Ibuf + ((T + 1) & 1) * TSZ + f_loc * RS);
            }
        } else {
            // ---------------- flush ----------------
            const int ft = tid - 192;
            const int r0 = ft >> 5, tq = ft & 31;    // warp covers full rows
            const float* ib  = Ibuf + buf * TSZ;
            const float* vpb = tvp + (buf ^ 1) * TSZ;
            const size_t tcol = (size_t)T * TILE + tq * 4;
            const size_t pcol = (size_t)(T - 1) * TILE + tq * 4;
            float4 mx = make_float4(-1e30f, -1e30f, -1e30f, -1e30f);
#pragma unroll
            for (int i = 0; i < 32; ++i) {
                const int r = r0 + 2 * i;
                const size_t grow = (size_t)(frow0 + r) * LL;
                float4 iq = *(const float4*)(ib + r * RS + tq * 4);
                stcs4(I_out + grow + tcol, iq);
                if (T >= 1) {
                    float4 vq = *(const float4*)(vpb + r * RS + tq * 4);
                    float4 sq, vn;
                    sq.x = (vq.x >= 1.0f) ? 1.0f : 0.0f;
                    sq.y = (vq.y >= 1.0f) ? 1.0f : 0.0f;
                    sq.z = (vq.z >= 1.0f) ? 1.0f : 0.0f;
                    sq.w = (vq.w >= 1.0f) ? 1.0f : 0.0f;
                    vn.x = (vq.x >= 1.0f) ? 0.0f : vq.x;
                    vn.y = (vq.y >= 1.0f) ? 0.0f : vq.y;
                    vn.z = (vq.z >= 1.0f) ? 0.0f : vq.z;
                    vn.w = (vq.w >= 1.0f) ? 0.0f : vq.w;
                    stcs4(vpre_out + grow + pcol, vq);
                    stcs4(v_out    + grow + pcol, vn);
                    stcs4(s_out    + grow + pcol, sq);
                    mx = max4(mx, vq);
                }
            }
            if (T >= 1) {
                *(float4*)(red + ft * 4) = mx;
                asm volatile("bar.sync 3, 64;" ::: "memory");
                if (ft < 32) {
                    float4 a  = *(float4*)(red + ft * 4);
                    float4 b4 = *(float4*)(red + (32 + ft) * 4);
                    a = max4(a, b4);
                    *(float4*)(prow + (size_t)(T - 1) * TILE + ft * 4) = a;
                }
            }
        }
        __syncthreads();
    }

    // ---- epilogue: flush v_pre/v/s + partial max of tile 63 (buffer 1) ----
    if (tid >= 192) {
        const int ft = tid - 192;
        const int r0 = ft >> 5, tq = ft & 31;
        const float* vpb = tvp + ((NTILES - 1) & 1) * TSZ;
        const size_t pcol = (size_t)(NTILES - 1) * TILE + tq * 4;
        float4 mx = make_float4(-1e30f, -1e30f, -1e30f, -1e30f);
#pragma unroll
        for (int i = 0; i < 32; ++i) {
            const int r = r0 + 2 * i;
            const size_t grow = (size_t)(frow0 + r) * LL;
            float4 vq = *(const float4*)(vpb + r * RS + tq * 4);
            float4 sq, vn;
            sq.x = (vq.x >= 1.0f) ? 1.0f : 0.0f;
            sq.y = (vq.y >= 1.0f) ? 1.0f : 0.0f;
            sq.z = (vq.z >= 1.0f) ? 1.0f : 0.0f;
            sq.w = (vq.w >= 1.0f) ? 1.0f : 0.0f;
            vn.x = (vq.x >= 1.0f) ? 0.0f : vq.x;
            vn.y = (vq.y >= 1.0f) ? 0.0f : vq.y;
            vn.z = (vq.z >= 1.0f) ? 0.0f : vq.z;
            vn.w = (vq.w >= 1.0f) ? 0.0f : vq.w;
            stcs4(vpre_out + grow + pcol, vq);
            stcs4(v_out    + grow + pcol, vn);
            stcs4(s_out    + grow + pcol, sq);
            mx = max4(mx, vq);
        }
        *(float4*)(red + ft * 4) = mx;
        asm volatile("bar.sync 3, 64;" ::: "memory");
        if (ft < 32) {
            float4 a  = *(float4*)(red + ft * 4);
            float4 b4 = *(float4*)(red + (32 + ft) * 4);
            a = max4(a, b4);
            *(float4*)(prow + (size_t)(NTILES - 1) * TILE + ft * 4) = a;
        }
    }
}

// ---------------------------------------------------------------------------
// Combine the two filter-half partial maxes into logits.
// MLP=4: each thread owns two float4 column-pairs (4 independent loads) so
// L2 latency (~234cyc) is double-covered; 65536 threads.
// ---------------------------------------------------------------------------
__global__ __launch_bounds__(256) void logits_kernel(float* __restrict__ logits)
{
    int i = blockIdx.x * blockDim.x + threadIdx.x;   // 0 .. BB*LL/8-1
    int b  = i >> 10;                                // 1024 pair-groups/batch
    int l4 = (i & 1023) * 2;                         // float4 index (even)
    const float4* p0 = (const float4*)(g_partial + (size_t)(2 * b) * LL) + l4;
    const float4* p1 = (const float4*)(g_partial + (size_t)(2 * b + 1) * LL) + l4;
    float4 a0 = p0[0], c0 = p1[0];
    float4 a1 = p0[1], c1 = p1[1];
    float4 m0 = max4(a0, c0);
    float4 m1 = max4(a1, c1);
    m0.x -= 1.0f; m0.y -= 1.0f; m0.z -= 1.0f; m0.w -= 1.0f;
    m1.x -= 1.0f; m1.y -= 1.0f; m1.z -= 1.0f; m1.w -= 1.0f;
    float* dst = logits + (size_t)b * LL + l4 * 4;
    stcs4(dst,     m0);
    stcs4(dst + 4, m1);
}

extern "C" void kernel_launch(void* const* d_in, const int* in_sizes, int n_in,
                              void* d_out, int out_size)
{
    const float* x    = (const float*)d_in[0];
    const float* W    = (const float*)d_in[1];
    const float* bias = (const float*)d_in[2];
    float* out = (float*)d_out;

    const size_t N = (size_t)BB * FF * LL;   // 67,108,864
    float* I    = out;
    float* vpre = out + N;
    float* vv   = out + 2 * N;
    float* ss   = out + 3 * N;
    float* lg   = out + 4 * N;

    const int smem_bytes = (4 * TSZ + 144 + 144 + 256) * sizeof(float); // ~137.4KB
    cudaFuncSetAttribute(snn_fused,
                         cudaFuncAttributeMaxDynamicSharedMemorySize, smem_bytes);

    snn_fused<<<128, 256, smem_bytes>>>(x, W, bias, I, vpre, vv, ss);
    logits_kernel<<<(BB * LL / 8) / 256, 256>>>(lg);
}